// round 15
// baseline (speedup 1.0000x reference)
#include <cuda_runtime.h>
#include <cuda_bf16.h>
#include <cstdint>

#define BB 4
#define HH 256
#define CC 80
#define TX 256
#define TY 1024
#define NEGV (-1e9f)

// Output layout (float32):
#define OFF_OEN  0
#define OFF_LOGP 1048576
#define OFF_ATTN 2097152
#define OFF_DR   3145728

// -------- device scratch --------
__device__ float g_A  [BB*CC*TX];   // -0.5/C * exp(-2 ls)
__device__ float g_Bc [BB*CC*TX];   //  1/C   * exp(-2 ls) * mu
__device__ float g_cst[BB*TX];      // -0.5/C * (sum w*mu^2 + sum ls)
__device__ float g_lpT[BB*TY*TX];   // masked logp, transposed [b][y][x]
__device__ int   g_idx[BB*TY];      // alignment index per y (-1 = inactive)
__device__ int   g_rdy[BB*32];      // per-(batch, 32-row ytile) completion count

__device__ __forceinline__ int ld_acq(const int* p) {
    int v;
    asm volatile("ld.acquire.gpu.global.s32 %0, [%1];" : "=r"(v) : "l"(p));
    return v;
}
__device__ __forceinline__ void wait_tile(const int* p) {
    if (ld_acq(p) >= 4) return;
    while (ld_acq(p) < 4) __nanosleep(40);
}

// =====================================================================
// K0: per-(b,x) channel precompute (once, not per logp tile)
// =====================================================================
__global__ void k_pre(const float* __restrict__ mu,
                      const float* __restrict__ ls) {
    int b = blockIdx.x;
    int x = threadIdx.x;
    float s3 = 0.f, sl = 0.f;
    #pragma unroll 4
    for (int c = 0; c < CC; c++) {
        int o = (b * CC + c) * TX + x;
        float l = ls[o];
        float m = mu[o];
        float w = expf(-2.0f * l);
        g_A [o] = (-0.5f / (float)CC) * w;
        g_Bc[o] = (1.0f / (float)CC) * w * m;
        s3 += w * m * m;
        sl += l;
    }
    g_cst[b * TX + x] = (-0.5f / (float)CC) * (s3 + sl);
}

// =====================================================================
// K1: logp GEMM, 64x32 tiles:  logp = (A*y + B)*y + cst
//     A/B/cst loaded from gmem (k_pre). bid0 offsets the tile index so
//     the kernel can be launched in early/late slices.
// smem layout (bytes):
//   sA[80][64]  @ 0      (20480)
//   sB[80][64]  @ 20480  (20480)
//   sY[80][32]  @ 40960  (10240)
//   scst[64]    @ 51200  (256)
// =====================================================================
#define LP_SMEM_BYTES 51456

__global__ __launch_bounds__(256, 4)
void k_logp(const float* __restrict__ y,
            const int* __restrict__ xl,
            const int* __restrict__ yl,
            float* __restrict__ out,
            int bid0) {
    extern __shared__ char sm[];
    float (*sA)[64] = (float(*)[64])(sm);
    float (*sB)[64] = (float(*)[64])(sm + 20480);
    float (*sY)[32] = (float(*)[32])(sm + 40960);
    float* scst     = (float*)(sm + 51200);

    int bid = blockIdx.x + bid0;
    int xt = bid & 3;
    int b  = (bid >> 2) & 3;
    int yt = bid >> 4;                 // 0..31
    int x0 = xt * 64;
    int y0 = yt * 32;
    int tid = threadIdx.x;

    // load A/B (80x64 each), cst (64), y (80x32)
    #pragma unroll
    for (int i = tid; i < 80 * 64 / 4; i += 256) {
        int c = i >> 4, j = (i & 15) * 4;    // 16 float4 per row
        int oa = (b * CC + c) * TX + x0 + j;
        *(float4*)&sA[c][j] = *(const float4*)&g_A[oa];
        *(float4*)&sB[c][j] = *(const float4*)&g_Bc[oa];
    }
    #pragma unroll
    for (int i = tid; i < 80 * 32; i += 256) {
        int c = i >> 5, j = i & 31;
        sY[c][j] = y[(b * CC + c) * TY + y0 + j];
    }
    if (tid < 64) scst[tid] = g_cst[b * TX + x0 + tid];
    __syncthreads();

    int ty = tid & 15;                 // 16 y-groups of 2
    int tx = tid >> 4;                 // 16 x-groups of 4
    int xr = tx * 4;
    int yc = ty * 2;

    float acc[4][2] = {};

    #pragma unroll 10
    for (int c = 0; c < CC; c++) {
        float4 a  = *(const float4*)&sA[c][xr];
        float4 bb = *(const float4*)&sB[c][xr];
        float2 yv = *(const float2*)&sY[c][yc];
        float av[4] = {a.x, a.y, a.z, a.w};
        float bv[4] = {bb.x, bb.y, bb.z, bb.w};
        float yvv[2] = {yv.x, yv.y};
        #pragma unroll
        for (int i = 0; i < 4; i++)
            #pragma unroll
            for (int j = 0; j < 2; j++) {
                float t = fmaf(av[i], yvv[j], bv[i]);
                acc[i][j] = fmaf(t, yvv[j], acc[i][j]);
            }
    }

    float cst_i[4];
    #pragma unroll
    for (int i = 0; i < 4; i++)
        cst_i[i] = scst[xr + i];

    int xlen = xl[b], ylen = yl[b];

    #pragma unroll
    for (int i = 0; i < 4; i++) {
        int gx = x0 + xr + i;
        float2 r;
        r.x = acc[i][0] + cst_i[i];
        r.y = acc[i][1] + cst_i[i];
        *(float2*)&out[OFF_LOGP + ((size_t)(b * TX + gx)) * TY + y0 + yc] = r;
    }

    #pragma unroll
    for (int j = 0; j < 2; j++) {
        int gy = y0 + yc + j;
        bool ym = gy < ylen;
        float4 t;
        t.x = (ym && (x0 + xr + 0) < xlen) ? acc[0][j] + cst_i[0] : NEGV;
        t.y = (ym && (x0 + xr + 1) < xlen) ? acc[1][j] + cst_i[1] : NEGV;
        t.z = (ym && (x0 + xr + 2) < xlen) ? acc[2][j] + cst_i[2] : NEGV;
        t.w = (ym && (x0 + xr + 3) < xlen) ? acc[3][j] + cst_i[3] : NEGV;
        *(float4*)&g_lpT[((size_t)(b * TY + gy)) * TX + x0 + xr] = t;
    }

    // publish tile completion
    __threadfence();
    __syncthreads();
    if (tid == 0) {
        __threadfence();
        atomicAdd(&g_rdy[b * 32 + yt], 1);
    }
}

// =====================================================================
// K2: Viterbi DP — r8 warp cascade, flag-gated __ldcg producers.
//     Runs CONCURRENTLY with k_logp.
// =====================================================================
#define DPC 32
// DP smem layout (bytes), r8-identical:
//   rows:  float4[3][32*64]  = 98304   @ 0
//   vring: float4[3][32*64]  = 98304   @ 98304
//   diag:  unsigned[32][256] = 32768   @ 196608
//   edge:  float[3][32]      = 384     @ 229376
//   dr:    int[256]          = 1024    @ 229760
//   cum:   int[257]          = 1028    @ 230784
#define DP_SMEM_BYTES 231812

__global__ __launch_bounds__(256, 1)
void k_dp(const int* __restrict__ xl,
          const int* __restrict__ yl,
          float* __restrict__ out) {
    extern __shared__ char smem[];
    float4*   rows  = (float4*)smem;                      // [3][2048]
    float4*   vring = (float4*)(smem + 98304);            // [3][2048]
    unsigned* diag  = (unsigned*)(smem + 196608);         // [32][256]
    float*    edge  = (float*)(smem + 229376);            // [3][32]
    int*      s_dr  = (int*)(smem + 229760);
    int*      s_cum = (int*)(smem + 230784);

    int b    = blockIdx.x;
    int tid  = threadIdx.x;
    int wid  = tid >> 5;
    int lane = tid & 31;

    int xlen = xl[b], ylen = yl[b];
    int nck  = (ylen + DPC - 1) / DPC;     // 16..32 chunks of 32 rows

    const float4* lp4 = (const float4*)(g_lpT + (size_t)b * TY * TX);

    s_dr[tid] = 0;

    // prologue: wait for tile (b,0), then stage chunk 0
    if (tid == 0) wait_tile(&g_rdy[b * 32]);
    __syncthreads();
    for (int i = tid; i < 2048; i += 256)
        rows[i] = __ldcg(lp4 + i);
    __syncthreads();

    if (wid == 7) {
        // -------- recurrence x in [0,128), chunk p --------
        float4 v = make_float4(NEGV, NEGV, NEGV, NEGV);
        if (lane == 0) v.x = 0.0f;
        bool l0 = (lane == 0), l31 = (lane == 31);

        #pragma unroll 1
        for (int p = 0; p < nck + 2; p++) {
            if (p < nck) {
                const float4* rb = rows  + (p % 3) * 2048;
                float4*       vr = vring + (p % 3) * 2048;
                float*        eC = edge + (p % 3) * 32;
                float4 c_cur = rb[lane];
                float4 c_nxt = rb[64 + lane];
                #pragma unroll
                for (int r = 0; r < 32; r++) {
                    float4 c_n2 = rb[((r < 30) ? (r + 2) * 64 : 0) + lane];
                    float top = __shfl_up_sync(0xffffffffu, v.w, 1);
                    if (l0) top = NEGV;
                    float4 nv;
                    nv.x = c_cur.x + fmaxf(v.x, top);
                    nv.y = c_cur.y + fmaxf(v.y, v.x);
                    nv.z = c_cur.z + fmaxf(v.z, v.y);
                    nv.w = c_cur.w + fmaxf(v.w, v.z);
                    v = nv;
                    vr[r * 64 + lane] = v;
                    if (l31) eC[r] = v.w;
                    c_cur = c_nxt; c_nxt = c_n2;
                }
            }
            __syncthreads();
        }
    } else if (wid == 6) {
        // -------- recurrence x in [128,256), chunk p-1 --------
        float4 v = make_float4(NEGV, NEGV, NEGV, NEGV);
        bool l0 = (lane == 0);
        float carry_e = NEGV;

        #pragma unroll 1
        for (int p = 0; p < nck + 2; p++) {
            int ck = p - 1;
            if (ck >= 0 && ck < nck) {
                const float4* rb = rows  + (ck % 3) * 2048;
                float4*       vr = vring + (ck % 3) * 2048;
                const float*  eC = edge + (ck % 3) * 32;
                float4 c_cur = rb[32 + lane];
                float4 c_nxt = rb[96 + lane];
                #pragma unroll
                for (int r = 0; r < 32; r++) {
                    float4 c_n2 = rb[((r < 30) ? (r + 2) * 64 : 0) + 32 + lane];
                    float e_cur = (r == 0) ? carry_e : eC[r - 1];
                    float top = __shfl_up_sync(0xffffffffu, v.w, 1);
                    if (l0) top = e_cur;
                    float4 nv;
                    nv.x = c_cur.x + fmaxf(v.x, top);
                    nv.y = c_cur.y + fmaxf(v.y, v.x);
                    nv.z = c_cur.z + fmaxf(v.z, v.y);
                    nv.w = c_cur.w + fmaxf(v.w, v.z);
                    v = nv;
                    vr[r * 64 + 32 + lane] = v;
                    c_cur = c_nxt; c_nxt = c_n2;
                }
                carry_e = eC[31];
            }
            __syncthreads();
        }
    } else if (wid == 5) {
        // -------- diag bits x in [0,128), chunk p-2 --------
        float4 P = make_float4(NEGV, NEGV, NEGV, NEGV);
        if (lane == 0) P.x = 0.0f;
        bool l0 = (lane == 0);

        #pragma unroll 1
        for (int p = 0; p < nck + 2; p++) {
            int ck = p - 2;
            if (ck >= 0) {
                const float4* vr = vring + (ck % 3) * 2048;
                unsigned db0 = 0, db1 = 0, db2 = 0, db3 = 0;
                #pragma unroll
                for (int r = 0; r < 32; r++) {
                    float4 V = vr[r * 64 + lane];
                    float pm1 = __shfl_up_sync(0xffffffffu, P.w, 1);
                    if (l0) pm1 = NEGV;
                    unsigned bit = 1u << r;
                    if (pm1 > P.x) db0 |= bit;
                    if (P.x > P.y) db1 |= bit;
                    if (P.y > P.z) db2 |= bit;
                    if (P.z > P.w) db3 |= bit;
                    P = V;
                }
                *(uint4*)&diag[ck * 256 + lane * 4] =
                    make_uint4(db0, db1, db2, db3);
            }
            __syncthreads();
        }
    } else if (wid == 4) {
        // -------- diag bits x in [128,256), chunk p-2 --------
        float4 P = make_float4(NEGV, NEGV, NEGV, NEGV);
        float s127 = NEGV;
        bool l0 = (lane == 0);

        #pragma unroll 1
        for (int p = 0; p < nck + 2; p++) {
            int ck = p - 2;
            if (ck >= 0) {
                const float4* vr = vring + (ck % 3) * 2048;
                unsigned db0 = 0, db1 = 0, db2 = 0, db3 = 0;
                #pragma unroll
                for (int r = 0; r < 32; r++) {
                    float4 V = vr[r * 64 + 32 + lane];
                    float s_new = ((const float*)(vr + r * 64))[127];
                    float pm1 = __shfl_up_sync(0xffffffffu, P.w, 1);
                    if (l0) pm1 = s127;
                    unsigned bit = 1u << r;
                    if (pm1 > P.x) db0 |= bit;
                    if (P.x > P.y) db1 |= bit;
                    if (P.y > P.z) db2 |= bit;
                    if (P.z > P.w) db3 |= bit;
                    P = V; s127 = s_new;
                }
                *(uint4*)&diag[ck * 256 + 128 + lane * 4] =
                    make_uint4(db0, db1, db2, db3);
            }
            __syncthreads();
        }
    } else {
        // -------- producers w0-3: quarter of chunk p+1, flag-gated --------
        #pragma unroll 1
        for (int p = 0; p < nck + 2; p++) {
            if (p + 1 < nck) {
                if (lane == 0) wait_tile(&g_rdy[b * 32 + (p + 1)]);
                __syncwarp();
                const float4* src = lp4 + (p + 1) * 2048 + wid * 512;
                float4* dst = rows + ((p + 1) % 3) * 2048 + wid * 512;
                float4 t[8];
                #pragma unroll
                for (int k = 0; k < 8; k++) t[k] = __ldcg(src + k * 32 + lane);
                #pragma unroll
                for (int k = 0; k < 8; k++) dst[k * 32 + lane] = t[k];
                #pragma unroll
                for (int k = 0; k < 8; k++) t[k] = __ldcg(src + 256 + k * 32 + lane);
                #pragma unroll
                for (int k = 0; k < 8; k++) dst[256 + k * 32 + lane] = t[k];
            }
            __syncthreads();
        }
    }
    __syncthreads();

    // ---- backtrack: run-length over diag words (lane 0) ----
    if (tid == 0) {
        int idx = xlen - 1;
        int yy  = ylen - 1;
        while (yy >= 0) {
            if (idx == 0) { s_dr[0] += yy + 1; break; }
            int yw = yy >> 5;
            unsigned mask = ((yy & 31) == 31) ? 0xffffffffu
                                              : ((2u << (yy & 31)) - 1u);
            unsigned m = diag[yw * 256 + idx] & mask;
            if (m) {
                int ystar = (yw << 5) + (31 - __clz(m));
                s_dr[idx] += yy - ystar + 1;
                idx--;
                yy = ystar - 1;
            } else {
                s_dr[idx] += yy - (yw << 5) + 1;
                yy = (yw << 5) - 1;
            }
        }
    }
    __syncthreads();

    // ---- exclusive cumsum of durations (warp 0) ----
    if (wid == 0) {
        int t[8], run[8];
        int tot = 0;
        #pragma unroll
        for (int i = 0; i < 8; i++) {
            t[i] = s_dr[lane * 8 + i];
            tot += t[i];
            run[i] = tot;
        }
        int sc = tot;
        #pragma unroll
        for (int d = 1; d < 32; d <<= 1) {
            int n = __shfl_up_sync(0xffffffffu, sc, d);
            if (lane >= d) sc += n;
        }
        int excl = sc - tot;
        if (lane == 0) s_cum[0] = 0;
        #pragma unroll
        for (int i = 0; i < 8; i++)
            s_cum[lane * 8 + i + 1] = excl + run[i];

        #pragma unroll
        for (int i = 0; i < 8; i++)
            out[OFF_DR + b * TX + lane * 8 + i] = (float)t[i];
    }
    __syncthreads();

    // ---- g_idx via binary search (4 y per thread) ----
    #pragma unroll
    for (int k = 0; k < TY / 256; k++) {
        int yy = k * 256 + tid;
        int r = -1;
        if (yy < ylen) {
            int lo = 0, hi = TX - 1;
            #pragma unroll
            for (int s = 0; s < 8; s++) {
                int mid = (lo + hi) >> 1;
                if (yy >= s_cum[mid + 1]) lo = mid + 1; else hi = mid;
            }
            r = lo;
        }
        g_idx[b * TY + yy] = r;
    }
}

// =====================================================================
// K3: fused epilogue — 4 rows per block; block 0 resets g_rdy for the
//     next graph replay (join guarantees logp/dp are done).
// =====================================================================
__global__ __launch_bounds__(256)
void k_epi(const float* __restrict__ en, float* __restrict__ out) {
    __shared__ float se[4][TX];
    int bid = blockIdx.x;
    int tid = threadIdx.x;
    int row0 = bid * 4;

    if (bid == 0 && tid < BB * 32) g_rdy[tid] = 0;

    if (row0 < BB * TX) {
        int b = row0 >> 8;
        int4 id = *(const int4*)&g_idx[b * TY + tid * 4];
        #pragma unroll
        for (int rr = 0; rr < 4; rr++) {
            int x = (row0 + rr) & 255;
            float4 r;
            r.x = (id.x == x) ? 1.0f : 0.0f;
            r.y = (id.y == x) ? 1.0f : 0.0f;
            r.z = (id.z == x) ? 1.0f : 0.0f;
            r.w = (id.w == x) ? 1.0f : 0.0f;
            *(float4*)&out[OFF_ATTN + (size_t)(row0 + rr) * TY + tid * 4] = r;
        }
    } else {
        int r0 = row0 - BB * TX;
        int b  = r0 >> 8;
        {
            int rr = tid >> 6;
            int h  = (r0 + rr) & 255;
            *(float4*)&se[rr][(tid & 63) * 4] =
                *(const float4*)&en[(b * HH + h) * TX + (tid & 63) * 4];
        }
        __syncthreads();
        int4 id = *(const int4*)&g_idx[b * TY + tid * 4];
        #pragma unroll
        for (int rr = 0; rr < 4; rr++) {
            float4 r;
            r.x = (id.x >= 0) ? se[rr][id.x] : 0.0f;
            r.y = (id.y >= 0) ? se[rr][id.y] : 0.0f;
            r.z = (id.z >= 0) ? se[rr][id.z] : 0.0f;
            r.w = (id.w >= 0) ? se[rr][id.w] : 0.0f;
            *(float4*)&out[OFF_OEN + (size_t)(r0 + rr) * TY + tid * 4] = r;
        }
    }
}

// =====================================================================
extern "C" void kernel_launch(void* const* d_in, const int* in_sizes, int n_in,
                              void* d_out, int out_size) {
    const float* en = (const float*)d_in[0];
    const float* mu = (const float*)d_in[1];
    const float* ls = (const float*)d_in[2];
    const float* y  = (const float*)d_in[3];
    const int*   xl = (const int*)d_in[4];
    const int*   yl = (const int*)d_in[5];
    float* out = (float*)d_out;

    static cudaStream_t s2 = nullptr;
    static cudaEvent_t evF = nullptr, evJ = nullptr;
    if (s2 == nullptr) {   // host-side handle init (first, non-captured call)
        cudaStreamCreateWithFlags(&s2, cudaStreamNonBlocking);
        cudaEventCreateWithFlags(&evF, cudaEventDisableTiming);
        cudaEventCreateWithFlags(&evJ, cudaEventDisableTiming);
        cudaFuncSetAttribute(k_logp, cudaFuncAttributeMaxDynamicSharedMemorySize,
                             LP_SMEM_BYTES);
        cudaFuncSetAttribute(k_dp, cudaFuncAttributeMaxDynamicSharedMemorySize,
                             DP_SMEM_BYTES);
    }

    // fork: precompute + staged logp on side stream (submitted FIRST so
    // any serialized execution order is deadlock-free), DP on main stream
    cudaEventRecord(evF, 0);
    cudaStreamWaitEvent(s2, evF, 0);
    k_pre<<<BB, TX, 0, s2>>>(mu, ls);
    k_logp<<<128, 256, LP_SMEM_BYTES, s2>>>(y, xl, yl, out, 0);    // yt 0..7
    k_logp<<<384, 256, LP_SMEM_BYTES, s2>>>(y, xl, yl, out, 128);  // yt 8..31

    k_dp<<<BB, 256, DP_SMEM_BYTES>>>(xl, yl, out);

    // join, then epilogue
    cudaEventRecord(evJ, s2);
    cudaStreamWaitEvent(0, evJ, 0);
    k_epi<<<2 * BB * TX / 4, 256>>>(en, out);
}

// round 16
// speedup vs baseline: 1.2140x; 1.2140x over previous
#include <cuda_runtime.h>
#include <cuda_bf16.h>
#include <cstdint>

#define BB 4
#define HH 256
#define CC 80
#define TX 256
#define TY 1024
#define NEGV (-1e9f)

// Output layout (float32):
#define OFF_OEN  0
#define OFF_LOGP 1048576
#define OFF_ATTN 2097152
#define OFF_DR   3145728

// -------- device scratch --------
__device__ float g_lpT[BB*TY*TX];   // masked logp, transposed [b][y][x]
__device__ int   g_idx[BB*TY];      // alignment index per y (-1 = inactive)
__device__ int   g_rdy[BB*32];      // per-(batch, 32-row ytile) completion count

__device__ __forceinline__ int ld_acq(const int* p) {
    int v;
    asm volatile("ld.acquire.gpu.global.s32 %0, [%1];" : "=r"(v) : "l"(p));
    return v;
}
__device__ __forceinline__ void wait_tile(const int* p) {
    if (ld_acq(p) >= 4) return;
    while (ld_acq(p) < 4) __nanosleep(40);
}
__device__ __forceinline__ void cp_async16(void* smem_dst, const void* gmem_src) {
    unsigned sa = (unsigned)__cvta_generic_to_shared(smem_dst);
    asm volatile("cp.async.cg.shared.global [%0], [%1], 16;\n"
                 :: "r"(sa), "l"(gmem_src));
}

// =====================================================================
// K1: logp GEMM, self-contained, 64x32 tiles (r14 version, best logp).
//   logp = (A*y + B)*y + cst   (A,B,cst computed in-block from mu/ls)
// smem layout (bytes):
//   sA[80][64]  @ 0      (20480)
//   sB[80][64]  @ 20480  (20480)
//   sY[80][32]  @ 40960  (10240)
//   scst[64]    @ 51200  (256)
//   spart[4][64]@ 51456  (1024)
// =====================================================================
#define LP_SMEM_BYTES 52480

__global__ __launch_bounds__(256, 4)
void k_logp(const float* __restrict__ mu,
            const float* __restrict__ ls,
            const float* __restrict__ y,
            const int* __restrict__ xl,
            const int* __restrict__ yl,
            float* __restrict__ out) {
    extern __shared__ char sm[];
    float (*sA)[64]    = (float(*)[64])(sm);
    float (*sB)[64]    = (float(*)[64])(sm + 20480);
    float (*sY)[32]    = (float(*)[32])(sm + 40960);
    float* scst        = (float*)(sm + 51200);
    float (*spart)[64] = (float(*)[64])(sm + 51456);

    int bid = blockIdx.x;
    int xt = bid & 3;
    int b  = (bid >> 2) & 3;
    int yt = bid >> 4;                 // 0..31
    int x0 = xt * 64;
    int y0 = yt * 32;
    int tid = threadIdx.x;

    // ---- phase A: per-(b,x) channel precompute ----
    {
        int xi  = tid & 63;
        int grp = tid >> 6;            // 0..3, 20 channels each
        float acc = 0.f;
        #pragma unroll 5
        for (int k = 0; k < 20; k++) {
            int c = grp * 20 + k;
            int o = (b * CC + c) * TX + x0 + xi;
            float l = ls[o];
            float m = mu[o];
            float w = expf(-2.0f * l);
            sA[c][xi] = (-0.5f / (float)CC) * w;
            sB[c][xi] = (1.0f / (float)CC) * w * m;
            acc += w * m * m + l;
        }
        spart[grp][xi] = acc;
    }
    #pragma unroll
    for (int i = tid; i < 80 * 32; i += 256) {
        int c = i >> 5, j = i & 31;
        sY[c][j] = y[(b * CC + c) * TY + y0 + j];
    }
    __syncthreads();
    if (tid < 64)
        scst[tid] = (-0.5f / (float)CC) *
                    (spart[0][tid] + spart[1][tid] + spart[2][tid] + spart[3][tid]);
    __syncthreads();

    int ty = tid & 15;
    int tx = tid >> 4;
    int xr = tx * 4;
    int yc = ty * 2;

    float acc[4][2] = {};

    #pragma unroll 10
    for (int c = 0; c < CC; c++) {
        float4 a  = *(const float4*)&sA[c][xr];
        float4 bb = *(const float4*)&sB[c][xr];
        float2 yv = *(const float2*)&sY[c][yc];
        float av[4] = {a.x, a.y, a.z, a.w};
        float bv[4] = {bb.x, bb.y, bb.z, bb.w};
        float yvv[2] = {yv.x, yv.y};
        #pragma unroll
        for (int i = 0; i < 4; i++)
            #pragma unroll
            for (int j = 0; j < 2; j++) {
                float t = fmaf(av[i], yvv[j], bv[i]);
                acc[i][j] = fmaf(t, yvv[j], acc[i][j]);
            }
    }

    float cst_i[4];
    #pragma unroll
    for (int i = 0; i < 4; i++)
        cst_i[i] = scst[xr + i];

    int xlen = xl[b], ylen = yl[b];

    #pragma unroll
    for (int i = 0; i < 4; i++) {
        int gx = x0 + xr + i;
        float2 r;
        r.x = acc[i][0] + cst_i[i];
        r.y = acc[i][1] + cst_i[i];
        *(float2*)&out[OFF_LOGP + ((size_t)(b * TX + gx)) * TY + y0 + yc] = r;
    }

    #pragma unroll
    for (int j = 0; j < 2; j++) {
        int gy = y0 + yc + j;
        bool ym = gy < ylen;
        float4 t;
        t.x = (ym && (x0 + xr + 0) < xlen) ? acc[0][j] + cst_i[0] : NEGV;
        t.y = (ym && (x0 + xr + 1) < xlen) ? acc[1][j] + cst_i[1] : NEGV;
        t.z = (ym && (x0 + xr + 2) < xlen) ? acc[2][j] + cst_i[2] : NEGV;
        t.w = (ym && (x0 + xr + 3) < xlen) ? acc[3][j] + cst_i[3] : NEGV;
        *(float4*)&g_lpT[((size_t)(b * TY + gy)) * TX + x0 + xr] = t;
    }

    // publish tile completion
    __threadfence();
    __syncthreads();
    if (tid == 0) {
        __threadfence();
        atomicAdd(&g_rdy[b * 32 + yt], 1);
    }
}

// =====================================================================
// K2: Viterbi DP — TRUE r8 4-warp x-split cascade (best measured DP),
//     flag-gated cp.async producer. 128 threads, one warp per SMSP.
//   w0: recurrence x[0,128),   chunk p
//   w1: recurrence x[128,256), chunk p-1 (edge from w0 via smem)
//   w2: cp.async producer chunk p+1 (flag-gated) + diag x[0,128) chunk p-2
//   w3: diag x[128,256) chunk p-2
// =====================================================================
#define DPC 32
// smem layout (bytes):
//   rows:  float4[3][32*64]  = 98304   @ 0
//   vring: float4[3][32*64]  = 98304   @ 98304
//   diag:  unsigned[32][256] = 32768   @ 196608
//   edge:  float[3][32]      = 384     @ 229376
//   dr:    int[256]          = 1024    @ 229760
//   cum:   int[257]          = 1028    @ 230784
#define DP_SMEM_BYTES 231812

__global__ __launch_bounds__(128, 1)
void k_dp(const int* __restrict__ xl,
          const int* __restrict__ yl,
          float* __restrict__ out) {
    extern __shared__ char smem[];
    float4*   rows  = (float4*)smem;                      // [3][2048]
    float4*   vring = (float4*)(smem + 98304);            // [3][2048]
    unsigned* diag  = (unsigned*)(smem + 196608);         // [32][256]
    float*    edge  = (float*)(smem + 229376);            // [3][32]
    int*      s_dr  = (int*)(smem + 229760);
    int*      s_cum = (int*)(smem + 230784);

    int b    = blockIdx.x;
    int tid  = threadIdx.x;
    int wid  = tid >> 5;
    int lane = tid & 31;

    int xlen = xl[b], ylen = yl[b];
    int nck  = (ylen + DPC - 1) / DPC;     // 16..32 chunks of 32 rows

    const float4* lp4 = (const float4*)(g_lpT + (size_t)b * TY * TX);

    s_dr[tid] = 0; s_dr[tid + 128] = 0;

    // prologue: wait for tile (b,0), then all threads stage chunk 0
    if (tid == 0) wait_tile(&g_rdy[b * 32]);
    __syncthreads();
    for (int i = tid; i < 2048; i += 128)
        rows[i] = __ldcg(lp4 + i);
    __syncthreads();

    if (wid == 0) {
        // -------- w0: recurrence x in [0,128), chunk p --------
        float4 v = make_float4(NEGV, NEGV, NEGV, NEGV);
        if (lane == 0) v.x = 0.0f;
        bool l0 = (lane == 0), l31 = (lane == 31);

        #pragma unroll 1
        for (int p = 0; p < nck + 2; p++) {
            if (p < nck) {
                const float4* rb = rows  + (p % 3) * 2048;
                float4*       vr = vring + (p % 3) * 2048;
                float*        eC = edge + (p % 3) * 32;
                float4 c_cur = rb[lane];
                float4 c_nxt = rb[64 + lane];
                #pragma unroll
                for (int r = 0; r < 32; r++) {
                    float4 c_n2 = rb[((r < 30) ? (r + 2) * 64 : 0) + lane];
                    float top = __shfl_up_sync(0xffffffffu, v.w, 1);
                    if (l0) top = NEGV;
                    float4 nv;
                    nv.x = c_cur.x + fmaxf(v.x, top);
                    nv.y = c_cur.y + fmaxf(v.y, v.x);
                    nv.z = c_cur.z + fmaxf(v.z, v.y);
                    nv.w = c_cur.w + fmaxf(v.w, v.z);
                    v = nv;
                    vr[r * 64 + lane] = v;
                    if (l31) eC[r] = v.w;
                    c_cur = c_nxt; c_nxt = c_n2;
                }
            }
            __syncthreads();
        }
    } else if (wid == 1) {
        // -------- w1: recurrence x in [128,256), chunk p-1 --------
        float4 v = make_float4(NEGV, NEGV, NEGV, NEGV);
        bool l0 = (lane == 0);
        float carry_e = NEGV;   // v[127] at row -1 (v_init[127] = NEG)

        #pragma unroll 1
        for (int p = 0; p < nck + 2; p++) {
            int ck = p - 1;
            if (ck >= 0 && ck < nck) {
                const float4* rb = rows  + (ck % 3) * 2048;
                float4*       vr = vring + (ck % 3) * 2048;
                const float*  eC = edge + (ck % 3) * 32;
                float4 c_cur = rb[32 + lane];
                float4 c_nxt = rb[96 + lane];
                #pragma unroll
                for (int r = 0; r < 32; r++) {
                    float4 c_n2 = rb[((r < 30) ? (r + 2) * 64 : 0) + 32 + lane];
                    float e_cur = (r == 0) ? carry_e : eC[r - 1];
                    float top = __shfl_up_sync(0xffffffffu, v.w, 1);
                    if (l0) top = e_cur;
                    float4 nv;
                    nv.x = c_cur.x + fmaxf(v.x, top);
                    nv.y = c_cur.y + fmaxf(v.y, v.x);
                    nv.z = c_cur.z + fmaxf(v.z, v.y);
                    nv.w = c_cur.w + fmaxf(v.w, v.z);
                    v = nv;
                    vr[r * 64 + 32 + lane] = v;
                    c_cur = c_nxt; c_nxt = c_n2;
                }
                carry_e = eC[31];
            }
            __syncthreads();
        }
    } else if (wid == 2) {
        // -------- w2: producer (chunk p+1, flag-gated) + diag x[0,128) --------
        float4 P = make_float4(NEGV, NEGV, NEGV, NEGV);   // v_init low
        if (lane == 0) P.x = 0.0f;
        bool l0 = (lane == 0);

        #pragma unroll 1
        for (int p = 0; p < nck + 2; p++) {
            if (p + 1 < nck) {
                if (l0) wait_tile(&g_rdy[b * 32 + (p + 1)]);
                __syncwarp();
                const float4* src = lp4 + (p + 1) * 2048;
                float4* dst = rows + ((p + 1) % 3) * 2048;
                #pragma unroll
                for (int i = 0; i < 64; i++)
                    cp_async16(dst + i * 32 + lane, src + i * 32 + lane);
                asm volatile("cp.async.commit_group;\n");
            }
            int ck = p - 2;
            if (ck >= 0) {
                const float4* vr = vring + (ck % 3) * 2048;
                unsigned db0 = 0, db1 = 0, db2 = 0, db3 = 0;
                #pragma unroll
                for (int r = 0; r < 32; r++) {
                    float4 C = vr[r * 64 + lane];
                    float pm1 = __shfl_up_sync(0xffffffffu, P.w, 1);
                    if (l0) pm1 = NEGV;
                    unsigned bit = 1u << r;
                    if (pm1 > P.x) db0 |= bit;
                    if (P.x > P.y) db1 |= bit;
                    if (P.y > P.z) db2 |= bit;
                    if (P.z > P.w) db3 |= bit;
                    P = C;
                }
                *(uint4*)&diag[ck * 256 + lane * 4] =
                    make_uint4(db0, db1, db2, db3);
            }
            if (p + 1 < nck)
                asm volatile("cp.async.wait_group 0;\n" ::: "memory");
            __syncthreads();
        }
    } else {
        // -------- w3: diag x[128,256) chunk p-2 --------
        float4 P = make_float4(NEGV, NEGV, NEGV, NEGV);   // v_init high
        float s127 = NEGV;                                 // v[127] @ row-1
        bool l0 = (lane == 0);

        #pragma unroll 1
        for (int p = 0; p < nck + 2; p++) {
            int ck = p - 2;
            if (ck >= 0) {
                const float4* vr = vring + (ck % 3) * 2048;
                unsigned db0 = 0, db1 = 0, db2 = 0, db3 = 0;
                #pragma unroll
                for (int r = 0; r < 32; r++) {
                    float4 C = vr[r * 64 + 32 + lane];
                    float pm1 = __shfl_up_sync(0xffffffffu, P.w, 1);
                    if (l0) pm1 = s127;
                    unsigned bit = 1u << r;
                    if (pm1 > P.x) db0 |= bit;
                    if (P.x > P.y) db1 |= bit;
                    if (P.y > P.z) db2 |= bit;
                    if (P.z > P.w) db3 |= bit;
                    P = C;
                    if (l0) s127 = ((const float*)(vr + r * 64))[127];
                }
                *(uint4*)&diag[ck * 256 + 128 + lane * 4] =
                    make_uint4(db0, db1, db2, db3);
            }
            __syncthreads();
        }
    }
    __syncthreads();

    // ---- backtrack: run-length over diag words (lane 0) ----
    if (tid == 0) {
        int idx = xlen - 1;
        int yy  = ylen - 1;
        while (yy >= 0) {
            if (idx == 0) { s_dr[0] += yy + 1; break; }
            int yw = yy >> 5;
            unsigned mask = ((yy & 31) == 31) ? 0xffffffffu
                                              : ((2u << (yy & 31)) - 1u);
            unsigned m = diag[yw * 256 + idx] & mask;
            if (m) {
                int ystar = (yw << 5) + (31 - __clz(m));
                s_dr[idx] += yy - ystar + 1;
                idx--;
                yy = ystar - 1;
            } else {
                s_dr[idx] += yy - (yw << 5) + 1;
                yy = (yw << 5) - 1;
            }
        }
    }
    __syncthreads();

    // ---- exclusive cumsum of durations (warp 0) ----
    if (wid == 0) {
        int t[8], run[8];
        int tot = 0;
        #pragma unroll
        for (int i = 0; i < 8; i++) {
            t[i] = s_dr[lane * 8 + i];
            tot += t[i];
            run[i] = tot;
        }
        int sc = tot;
        #pragma unroll
        for (int d = 1; d < 32; d <<= 1) {
            int n = __shfl_up_sync(0xffffffffu, sc, d);
            if (lane >= d) sc += n;
        }
        int excl = sc - tot;
        if (lane == 0) s_cum[0] = 0;
        #pragma unroll
        for (int i = 0; i < 8; i++)
            s_cum[lane * 8 + i + 1] = excl + run[i];

        #pragma unroll
        for (int i = 0; i < 8; i++)
            out[OFF_DR + b * TX + lane * 8 + i] = (float)t[i];
    }
    __syncthreads();

    // ---- g_idx via binary search (8 y per thread) ----
    #pragma unroll
    for (int k = 0; k < TY / 128; k++) {
        int yy = k * 128 + tid;
        int r = -1;
        if (yy < ylen) {
            int lo = 0, hi = TX - 1;
            #pragma unroll
            for (int s = 0; s < 8; s++) {
                int mid = (lo + hi) >> 1;
                if (yy >= s_cum[mid + 1]) lo = mid + 1; else hi = mid;
            }
            r = lo;
        }
        g_idx[b * TY + yy] = r;
    }
}

// =====================================================================
// K3: fused epilogue — 4 rows per block; block 0 resets g_rdy for the
//     next graph replay (join guarantees logp/dp are done).
// =====================================================================
__global__ __launch_bounds__(256)
void k_epi(const float* __restrict__ en, float* __restrict__ out) {
    __shared__ float se[4][TX];
    int bid = blockIdx.x;
    int tid = threadIdx.x;
    int row0 = bid * 4;

    if (bid == 0 && tid < BB * 32) g_rdy[tid] = 0;

    if (row0 < BB * TX) {
        int b = row0 >> 8;
        int4 id = *(const int4*)&g_idx[b * TY + tid * 4];
        #pragma unroll
        for (int rr = 0; rr < 4; rr++) {
            int x = (row0 + rr) & 255;
            float4 r;
            r.x = (id.x == x) ? 1.0f : 0.0f;
            r.y = (id.y == x) ? 1.0f : 0.0f;
            r.z = (id.z == x) ? 1.0f : 0.0f;
            r.w = (id.w == x) ? 1.0f : 0.0f;
            *(float4*)&out[OFF_ATTN + (size_t)(row0 + rr) * TY + tid * 4] = r;
        }
    } else {
        int r0 = row0 - BB * TX;
        int b  = r0 >> 8;
        {
            int rr = tid >> 6;
            int h  = (r0 + rr) & 255;
            *(float4*)&se[rr][(tid & 63) * 4] =
                *(const float4*)&en[(b * HH + h) * TX + (tid & 63) * 4];
        }
        __syncthreads();
        int4 id = *(const int4*)&g_idx[b * TY + tid * 4];
        #pragma unroll
        for (int rr = 0; rr < 4; rr++) {
            float4 r;
            r.x = (id.x >= 0) ? se[rr][id.x] : 0.0f;
            r.y = (id.y >= 0) ? se[rr][id.y] : 0.0f;
            r.z = (id.z >= 0) ? se[rr][id.z] : 0.0f;
            r.w = (id.w >= 0) ? se[rr][id.w] : 0.0f;
            *(float4*)&out[OFF_OEN + (size_t)(r0 + rr) * TY + tid * 4] = r;
        }
    }
}

// =====================================================================
extern "C" void kernel_launch(void* const* d_in, const int* in_sizes, int n_in,
                              void* d_out, int out_size) {
    const float* en = (const float*)d_in[0];
    const float* mu = (const float*)d_in[1];
    const float* ls = (const float*)d_in[2];
    const float* y  = (const float*)d_in[3];
    const int*   xl = (const int*)d_in[4];
    const int*   yl = (const int*)d_in[5];
    float* out = (float*)d_out;

    static cudaStream_t s2 = nullptr;
    static cudaEvent_t evF = nullptr, evJ = nullptr;
    if (s2 == nullptr) {   // host-side handle init (first, non-captured call)
        cudaStreamCreateWithFlags(&s2, cudaStreamNonBlocking);
        cudaEventCreateWithFlags(&evF, cudaEventDisableTiming);
        cudaEventCreateWithFlags(&evJ, cudaEventDisableTiming);
        cudaFuncSetAttribute(k_logp, cudaFuncAttributeMaxDynamicSharedMemorySize,
                             LP_SMEM_BYTES);
        cudaFuncSetAttribute(k_dp, cudaFuncAttributeMaxDynamicSharedMemorySize,
                             DP_SMEM_BYTES);
    }

    // fork: logp on side stream (submitted FIRST so any serialized
    // execution order is deadlock-free), DP concurrently on main stream
    cudaEventRecord(evF, 0);
    cudaStreamWaitEvent(s2, evF, 0);
    k_logp<<<512, 256, LP_SMEM_BYTES, s2>>>(mu, ls, y, xl, yl, out);

    k_dp<<<BB, 128, DP_SMEM_BYTES>>>(xl, yl, out);

    // join, then epilogue
    cudaEventRecord(evJ, s2);
    cudaStreamWaitEvent(0, evJ, 0);
    k_epi<<<2 * BB * TX / 4, 256>>>(en, out);
}

// round 17
// speedup vs baseline: 1.2445x; 1.0252x over previous
#include <cuda_runtime.h>
#include <cuda_bf16.h>
#include <cstdint>

#define BB 4
#define HH 256
#define CC 80
#define TX 256
#define TY 1024
#define NEGV (-1e9f)

// Output layout (float32):
#define OFF_OEN  0
#define OFF_LOGP 1048576
#define OFF_ATTN 2097152
#define OFF_DR   3145728

// -------- device scratch --------
__device__ float g_A  [BB*CC*TX];   // -0.5/C * exp(-2 ls)
__device__ float g_Bc [BB*CC*TX];   //  1/C   * exp(-2 ls) * mu
__device__ float g_cst[BB*TX];      // -0.5/C * (sum w*mu^2 + sum ls)
__device__ float g_lpT[BB*TY*TX];   // masked logp, transposed [b][y][x]
__device__ int   g_idx[BB*TY];      // alignment index per y (-1 = inactive)
__device__ int   g_rdy[BB*32];      // per-(batch, 32-row ytile) completion count

__device__ __forceinline__ int ld_acq(const int* p) {
    int v;
    asm volatile("ld.acquire.gpu.global.s32 %0, [%1];" : "=r"(v) : "l"(p));
    return v;
}
__device__ __forceinline__ void wait_tile(const int* p) {
    if (ld_acq(p) >= 4) return;
    while (ld_acq(p) < 4) __nanosleep(40);
}
__device__ __forceinline__ void cp_async16(void* smem_dst, const void* gmem_src) {
    unsigned sa = (unsigned)__cvta_generic_to_shared(smem_dst);
    asm volatile("cp.async.cg.shared.global [%0], [%1], 16;\n"
                 :: "r"(sa), "l"(gmem_src));
}

// =====================================================================
// K0: channel precompute, WIDE (64 blocks so MUFU is chip-parallel).
//     Block = (b, 16-x group); 256 threads = 16 x * 16 c-groups (5 c each).
// =====================================================================
__global__ __launch_bounds__(256)
void k_pre(const float* __restrict__ mu,
           const float* __restrict__ ls) {
    __shared__ float spart[16][17];
    int blk = blockIdx.x;
    int b  = blk >> 4;
    int x0 = (blk & 15) * 16;
    int tid = threadIdx.x;
    int xi = tid & 15;
    int cg = tid >> 4;                 // 0..15, 5 channels each

    float acc = 0.f;
    #pragma unroll
    for (int k = 0; k < 5; k++) {
        int c = cg * 5 + k;
        int o = (b * CC + c) * TX + x0 + xi;
        float l = ls[o];
        float m = mu[o];
        float w = expf(-2.0f * l);
        g_A [o] = (-0.5f / (float)CC) * w;
        g_Bc[o] = (1.0f / (float)CC) * w * m;
        acc += w * m * m + l;
    }
    spart[cg][xi] = acc;
    __syncthreads();
    if (tid < 16) {
        float s = 0.f;
        #pragma unroll
        for (int g = 0; g < 16; g++) s += spart[g][tid];
        g_cst[b * TX + x0 + tid] = (-0.5f / (float)CC) * s;
    }
}

// =====================================================================
// K1: logp GEMM, 64x32 tiles:  logp = (A*y + B)*y + cst
//     A/B/cst loaded from gmem (k_pre) — no per-tile exp.
// smem layout (bytes):
//   sA[80][64]  @ 0      (20480)
//   sB[80][64]  @ 20480  (20480)
//   sY[80][32]  @ 40960  (10240)
//   scst[64]    @ 51200  (256)
// =====================================================================
#define LP_SMEM_BYTES 51456

__global__ __launch_bounds__(256, 4)
void k_logp(const float* __restrict__ y,
            const int* __restrict__ xl,
            const int* __restrict__ yl,
            float* __restrict__ out) {
    extern __shared__ char sm[];
    float (*sA)[64] = (float(*)[64])(sm);
    float (*sB)[64] = (float(*)[64])(sm + 20480);
    float (*sY)[32] = (float(*)[32])(sm + 40960);
    float* scst     = (float*)(sm + 51200);

    int bid = blockIdx.x;
    int xt = bid & 3;
    int b  = (bid >> 2) & 3;
    int yt = bid >> 4;                 // 0..31
    int x0 = xt * 64;
    int y0 = yt * 32;
    int tid = threadIdx.x;

    // load A/B (80x64 each), cst (64), y (80x32)
    #pragma unroll
    for (int i = tid; i < 80 * 64 / 4; i += 256) {
        int c = i >> 4, j = (i & 15) * 4;    // 16 float4 per row
        int oa = (b * CC + c) * TX + x0 + j;
        *(float4*)&sA[c][j] = *(const float4*)&g_A[oa];
        *(float4*)&sB[c][j] = *(const float4*)&g_Bc[oa];
    }
    #pragma unroll
    for (int i = tid; i < 80 * 32; i += 256) {
        int c = i >> 5, j = i & 31;
        sY[c][j] = y[(b * CC + c) * TY + y0 + j];
    }
    if (tid < 64) scst[tid] = g_cst[b * TX + x0 + tid];
    __syncthreads();

    int ty = tid & 15;                 // 16 y-groups of 2
    int tx = tid >> 4;                 // 16 x-groups of 4
    int xr = tx * 4;
    int yc = ty * 2;

    float acc[4][2] = {};

    #pragma unroll 10
    for (int c = 0; c < CC; c++) {
        float4 a  = *(const float4*)&sA[c][xr];
        float4 bb = *(const float4*)&sB[c][xr];
        float2 yv = *(const float2*)&sY[c][yc];
        float av[4] = {a.x, a.y, a.z, a.w};
        float bv[4] = {bb.x, bb.y, bb.z, bb.w};
        float yvv[2] = {yv.x, yv.y};
        #pragma unroll
        for (int i = 0; i < 4; i++)
            #pragma unroll
            for (int j = 0; j < 2; j++) {
                float t = fmaf(av[i], yvv[j], bv[i]);
                acc[i][j] = fmaf(t, yvv[j], acc[i][j]);
            }
    }

    float cst_i[4];
    #pragma unroll
    for (int i = 0; i < 4; i++)
        cst_i[i] = scst[xr + i];

    int xlen = xl[b], ylen = yl[b];

    #pragma unroll
    for (int i = 0; i < 4; i++) {
        int gx = x0 + xr + i;
        float2 r;
        r.x = acc[i][0] + cst_i[i];
        r.y = acc[i][1] + cst_i[i];
        *(float2*)&out[OFF_LOGP + ((size_t)(b * TX + gx)) * TY + y0 + yc] = r;
    }

    #pragma unroll
    for (int j = 0; j < 2; j++) {
        int gy = y0 + yc + j;
        bool ym = gy < ylen;
        float4 t;
        t.x = (ym && (x0 + xr + 0) < xlen) ? acc[0][j] + cst_i[0] : NEGV;
        t.y = (ym && (x0 + xr + 1) < xlen) ? acc[1][j] + cst_i[1] : NEGV;
        t.z = (ym && (x0 + xr + 2) < xlen) ? acc[2][j] + cst_i[2] : NEGV;
        t.w = (ym && (x0 + xr + 3) < xlen) ? acc[3][j] + cst_i[3] : NEGV;
        *(float4*)&g_lpT[((size_t)(b * TY + gy)) * TX + x0 + xr] = t;
    }

    // publish tile completion
    __threadfence();
    __syncthreads();
    if (tid == 0) {
        __threadfence();
        atomicAdd(&g_rdy[b * 32 + yt], 1);
    }
}

// =====================================================================
// K2: Viterbi DP — r8 4-warp x-split cascade, flag-gated cp.async
//     producer. 128 threads, one warp per SMSP. (unchanged from r16)
// =====================================================================
#define DPC 32
// smem layout (bytes):
//   rows:  float4[3][32*64]  = 98304   @ 0
//   vring: float4[3][32*64]  = 98304   @ 98304
//   diag:  unsigned[32][256] = 32768   @ 196608
//   edge:  float[3][32]      = 384     @ 229376
//   dr:    int[256]          = 1024    @ 229760
//   cum:   int[257]          = 1028    @ 230784
#define DP_SMEM_BYTES 231812

__global__ __launch_bounds__(128, 1)
void k_dp(const int* __restrict__ xl,
          const int* __restrict__ yl,
          float* __restrict__ out) {
    extern __shared__ char smem[];
    float4*   rows  = (float4*)smem;                      // [3][2048]
    float4*   vring = (float4*)(smem + 98304);            // [3][2048]
    unsigned* diag  = (unsigned*)(smem + 196608);         // [32][256]
    float*    edge  = (float*)(smem + 229376);            // [3][32]
    int*      s_dr  = (int*)(smem + 229760);
    int*      s_cum = (int*)(smem + 230784);

    int b    = blockIdx.x;
    int tid  = threadIdx.x;
    int wid  = tid >> 5;
    int lane = tid & 31;

    int xlen = xl[b], ylen = yl[b];
    int nck  = (ylen + DPC - 1) / DPC;     // 16..32 chunks of 32 rows

    const float4* lp4 = (const float4*)(g_lpT + (size_t)b * TY * TX);

    s_dr[tid] = 0; s_dr[tid + 128] = 0;

    // prologue: wait for tile (b,0), then all threads stage chunk 0
    if (tid == 0) wait_tile(&g_rdy[b * 32]);
    __syncthreads();
    for (int i = tid; i < 2048; i += 128)
        rows[i] = __ldcg(lp4 + i);
    __syncthreads();

    if (wid == 0) {
        // -------- w0: recurrence x in [0,128), chunk p --------
        float4 v = make_float4(NEGV, NEGV, NEGV, NEGV);
        if (lane == 0) v.x = 0.0f;
        bool l0 = (lane == 0), l31 = (lane == 31);

        #pragma unroll 1
        for (int p = 0; p < nck + 2; p++) {
            if (p < nck) {
                const float4* rb = rows  + (p % 3) * 2048;
                float4*       vr = vring + (p % 3) * 2048;
                float*        eC = edge + (p % 3) * 32;
                float4 c_cur = rb[lane];
                float4 c_nxt = rb[64 + lane];
                #pragma unroll
                for (int r = 0; r < 32; r++) {
                    float4 c_n2 = rb[((r < 30) ? (r + 2) * 64 : 0) + lane];
                    float top = __shfl_up_sync(0xffffffffu, v.w, 1);
                    if (l0) top = NEGV;
                    float4 nv;
                    nv.x = c_cur.x + fmaxf(v.x, top);
                    nv.y = c_cur.y + fmaxf(v.y, v.x);
                    nv.z = c_cur.z + fmaxf(v.z, v.y);
                    nv.w = c_cur.w + fmaxf(v.w, v.z);
                    v = nv;
                    vr[r * 64 + lane] = v;
                    if (l31) eC[r] = v.w;
                    c_cur = c_nxt; c_nxt = c_n2;
                }
            }
            __syncthreads();
        }
    } else if (wid == 1) {
        // -------- w1: recurrence x in [128,256), chunk p-1 --------
        float4 v = make_float4(NEGV, NEGV, NEGV, NEGV);
        bool l0 = (lane == 0);
        float carry_e = NEGV;   // v[127] at row -1 (v_init[127] = NEG)

        #pragma unroll 1
        for (int p = 0; p < nck + 2; p++) {
            int ck = p - 1;
            if (ck >= 0 && ck < nck) {
                const float4* rb = rows  + (ck % 3) * 2048;
                float4*       vr = vring + (ck % 3) * 2048;
                const float*  eC = edge + (ck % 3) * 32;
                float4 c_cur = rb[32 + lane];
                float4 c_nxt = rb[96 + lane];
                #pragma unroll
                for (int r = 0; r < 32; r++) {
                    float4 c_n2 = rb[((r < 30) ? (r + 2) * 64 : 0) + 32 + lane];
                    float e_cur = (r == 0) ? carry_e : eC[r - 1];
                    float top = __shfl_up_sync(0xffffffffu, v.w, 1);
                    if (l0) top = e_cur;
                    float4 nv;
                    nv.x = c_cur.x + fmaxf(v.x, top);
                    nv.y = c_cur.y + fmaxf(v.y, v.x);
                    nv.z = c_cur.z + fmaxf(v.z, v.y);
                    nv.w = c_cur.w + fmaxf(v.w, v.z);
                    v = nv;
                    vr[r * 64 + 32 + lane] = v;
                    c_cur = c_nxt; c_nxt = c_n2;
                }
                carry_e = eC[31];
            }
            __syncthreads();
        }
    } else if (wid == 2) {
        // -------- w2: producer (chunk p+1, flag-gated) + diag x[0,128) --------
        float4 P = make_float4(NEGV, NEGV, NEGV, NEGV);   // v_init low
        if (lane == 0) P.x = 0.0f;
        bool l0 = (lane == 0);

        #pragma unroll 1
        for (int p = 0; p < nck + 2; p++) {
            if (p + 1 < nck) {
                if (l0) wait_tile(&g_rdy[b * 32 + (p + 1)]);
                __syncwarp();
                const float4* src = lp4 + (p + 1) * 2048;
                float4* dst = rows + ((p + 1) % 3) * 2048;
                #pragma unroll
                for (int i = 0; i < 64; i++)
                    cp_async16(dst + i * 32 + lane, src + i * 32 + lane);
                asm volatile("cp.async.commit_group;\n");
            }
            int ck = p - 2;
            if (ck >= 0) {
                const float4* vr = vring + (ck % 3) * 2048;
                unsigned db0 = 0, db1 = 0, db2 = 0, db3 = 0;
                #pragma unroll
                for (int r = 0; r < 32; r++) {
                    float4 C = vr[r * 64 + lane];
                    float pm1 = __shfl_up_sync(0xffffffffu, P.w, 1);
                    if (l0) pm1 = NEGV;
                    unsigned bit = 1u << r;
                    if (pm1 > P.x) db0 |= bit;
                    if (P.x > P.y) db1 |= bit;
                    if (P.y > P.z) db2 |= bit;
                    if (P.z > P.w) db3 |= bit;
                    P = C;
                }
                *(uint4*)&diag[ck * 256 + lane * 4] =
                    make_uint4(db0, db1, db2, db3);
            }
            if (p + 1 < nck)
                asm volatile("cp.async.wait_group 0;\n" ::: "memory");
            __syncthreads();
        }
    } else {
        // -------- w3: diag x[128,256) chunk p-2 --------
        float4 P = make_float4(NEGV, NEGV, NEGV, NEGV);   // v_init high
        float s127 = NEGV;                                 // v[127] @ row-1
        bool l0 = (lane == 0);

        #pragma unroll 1
        for (int p = 0; p < nck + 2; p++) {
            int ck = p - 2;
            if (ck >= 0) {
                const float4* vr = vring + (ck % 3) * 2048;
                unsigned db0 = 0, db1 = 0, db2 = 0, db3 = 0;
                #pragma unroll
                for (int r = 0; r < 32; r++) {
                    float4 C = vr[r * 64 + 32 + lane];
                    float pm1 = __shfl_up_sync(0xffffffffu, P.w, 1);
                    if (l0) pm1 = s127;
                    unsigned bit = 1u << r;
                    if (pm1 > P.x) db0 |= bit;
                    if (P.x > P.y) db1 |= bit;
                    if (P.y > P.z) db2 |= bit;
                    if (P.z > P.w) db3 |= bit;
                    P = C;
                    if (l0) s127 = ((const float*)(vr + r * 64))[127];
                }
                *(uint4*)&diag[ck * 256 + 128 + lane * 4] =
                    make_uint4(db0, db1, db2, db3);
            }
            __syncthreads();
        }
    }
    __syncthreads();

    // ---- backtrack: run-length over diag words (lane 0) ----
    if (tid == 0) {
        int idx = xlen - 1;
        int yy  = ylen - 1;
        while (yy >= 0) {
            if (idx == 0) { s_dr[0] += yy + 1; break; }
            int yw = yy >> 5;
            unsigned mask = ((yy & 31) == 31) ? 0xffffffffu
                                              : ((2u << (yy & 31)) - 1u);
            unsigned m = diag[yw * 256 + idx] & mask;
            if (m) {
                int ystar = (yw << 5) + (31 - __clz(m));
                s_dr[idx] += yy - ystar + 1;
                idx--;
                yy = ystar - 1;
            } else {
                s_dr[idx] += yy - (yw << 5) + 1;
                yy = (yw << 5) - 1;
            }
        }
    }
    __syncthreads();

    // ---- exclusive cumsum of durations (warp 0) ----
    if (wid == 0) {
        int t[8], run[8];
        int tot = 0;
        #pragma unroll
        for (int i = 0; i < 8; i++) {
            t[i] = s_dr[lane * 8 + i];
            tot += t[i];
            run[i] = tot;
        }
        int sc = tot;
        #pragma unroll
        for (int d = 1; d < 32; d <<= 1) {
            int n = __shfl_up_sync(0xffffffffu, sc, d);
            if (lane >= d) sc += n;
        }
        int excl = sc - tot;
        if (lane == 0) s_cum[0] = 0;
        #pragma unroll
        for (int i = 0; i < 8; i++)
            s_cum[lane * 8 + i + 1] = excl + run[i];

        #pragma unroll
        for (int i = 0; i < 8; i++)
            out[OFF_DR + b * TX + lane * 8 + i] = (float)t[i];
    }
    __syncthreads();

    // ---- g_idx via binary search (8 y per thread) ----
    #pragma unroll
    for (int k = 0; k < TY / 128; k++) {
        int yy = k * 128 + tid;
        int r = -1;
        if (yy < ylen) {
            int lo = 0, hi = TX - 1;
            #pragma unroll
            for (int s = 0; s < 8; s++) {
                int mid = (lo + hi) >> 1;
                if (yy >= s_cum[mid + 1]) lo = mid + 1; else hi = mid;
            }
            r = lo;
        }
        g_idx[b * TY + yy] = r;
    }
}

// =====================================================================
// K3: fused epilogue — 4 rows per block; block 0 resets g_rdy for the
//     next graph replay (join guarantees logp/dp are done).
// =====================================================================
__global__ __launch_bounds__(256)
void k_epi(const float* __restrict__ en, float* __restrict__ out) {
    __shared__ float se[4][TX];
    int bid = blockIdx.x;
    int tid = threadIdx.x;
    int row0 = bid * 4;

    if (bid == 0 && tid < BB * 32) g_rdy[tid] = 0;

    if (row0 < BB * TX) {
        int b = row0 >> 8;
        int4 id = *(const int4*)&g_idx[b * TY + tid * 4];
        #pragma unroll
        for (int rr = 0; rr < 4; rr++) {
            int x = (row0 + rr) & 255;
            float4 r;
            r.x = (id.x == x) ? 1.0f : 0.0f;
            r.y = (id.y == x) ? 1.0f : 0.0f;
            r.z = (id.z == x) ? 1.0f : 0.0f;
            r.w = (id.w == x) ? 1.0f : 0.0f;
            *(float4*)&out[OFF_ATTN + (size_t)(row0 + rr) * TY + tid * 4] = r;
        }
    } else {
        int r0 = row0 - BB * TX;
        int b  = r0 >> 8;
        {
            int rr = tid >> 6;
            int h  = (r0 + rr) & 255;
            *(float4*)&se[rr][(tid & 63) * 4] =
                *(const float4*)&en[(b * HH + h) * TX + (tid & 63) * 4];
        }
        __syncthreads();
        int4 id = *(const int4*)&g_idx[b * TY + tid * 4];
        #pragma unroll
        for (int rr = 0; rr < 4; rr++) {
            float4 r;
            r.x = (id.x >= 0) ? se[rr][id.x] : 0.0f;
            r.y = (id.y >= 0) ? se[rr][id.y] : 0.0f;
            r.z = (id.z >= 0) ? se[rr][id.z] : 0.0f;
            r.w = (id.w >= 0) ? se[rr][id.w] : 0.0f;
            *(float4*)&out[OFF_OEN + (size_t)(r0 + rr) * TY + tid * 4] = r;
        }
    }
}

// =====================================================================
extern "C" void kernel_launch(void* const* d_in, const int* in_sizes, int n_in,
                              void* d_out, int out_size) {
    const float* en = (const float*)d_in[0];
    const float* mu = (const float*)d_in[1];
    const float* ls = (const float*)d_in[2];
    const float* y  = (const float*)d_in[3];
    const int*   xl = (const int*)d_in[4];
    const int*   yl = (const int*)d_in[5];
    float* out = (float*)d_out;

    static cudaStream_t s2 = nullptr;
    static cudaEvent_t evF = nullptr, evJ = nullptr;
    if (s2 == nullptr) {   // host-side handle init (first, non-captured call)
        cudaStreamCreateWithFlags(&s2, cudaStreamNonBlocking);
        cudaEventCreateWithFlags(&evF, cudaEventDisableTiming);
        cudaEventCreateWithFlags(&evJ, cudaEventDisableTiming);
        cudaFuncSetAttribute(k_logp, cudaFuncAttributeMaxDynamicSharedMemorySize,
                             LP_SMEM_BYTES);
        cudaFuncSetAttribute(k_dp, cudaFuncAttributeMaxDynamicSharedMemorySize,
                             DP_SMEM_BYTES);
    }

    // fork: wide k_pre + single-wave logp on side stream (submitted FIRST
    // so any serialized execution order is deadlock-free), DP on main stream
    cudaEventRecord(evF, 0);
    cudaStreamWaitEvent(s2, evF, 0);
    k_pre<<<BB * 16, 256, 0, s2>>>(mu, ls);
    k_logp<<<512, 256, LP_SMEM_BYTES, s2>>>(y, xl, yl, out);

    k_dp<<<BB, 128, DP_SMEM_BYTES>>>(xl, yl, out);

    // join, then epilogue
    cudaEventRecord(evJ, s2);
    cudaStreamWaitEvent(0, evJ, 0);
    k_epi<<<2 * BB * TX / 4, 256>>>(en, out);
}